// round 14
// baseline (speedup 1.0000x reference)
#include <cuda_runtime.h>
#include <cuda_fp16.h>
#include <cstddef>
#include <cstdint>

#define NPROJ 180
#define DH    192
#define DW    384
#define NX    96
#define NY    96
#define NZ    96
#define ZPT   4
#define PHW   ((size_t)NPROJ * DH * DW)

// Scratch: batch-fused bilinear quads at each (p, v, u):
//   .x = (b0: t[v][u], t[v][u+1])   .y = (b0: t[v+1][u], t[v+1][u+1])
//   .z = (b1: t[v][u], t[v][u+1])   .w = (b1: t[v+1][u], t[v+1][u+1])
// One LDG.128 fetches the full 2x2 footprint for BOTH batches. ~212 MB.
__device__ uint4 g_q[PHW];

__device__ __forceinline__ uint32_t h2_bits(__half2 h) {
    union { __half2 h; uint32_t u; } c; c.h = h; return c.u;
}
__device__ __forceinline__ __half2 bits_h2(uint32_t u) {
    union { uint32_t u; __half2 h; } c; c.u = u; return c.h;
}

__global__ void prep_quads(const float* __restrict__ sino) {
    size_t base = ((size_t)blockIdx.x * blockDim.x + threadIdx.x) * 4;
    if (base >= PHW) return;

    int v   = (int)((base / DW) % DH);
    int col = (int)(base % DW);
    bool lastv = (v == DH - 1);
    bool lastc = (col == DW - 4);

    float4 a0 = *(const float4*)(sino + base);
    float  a0n = lastc ? a0.w : __ldg(sino + base + 4);
    float4 c0; float c0n;
    if (!lastv) { c0 = *(const float4*)(sino + base + DW);
                  c0n = lastc ? c0.w : __ldg(sino + base + DW + 4); }
    else        { c0 = a0; c0n = a0n; }

    float4 a1 = *(const float4*)(sino + base + PHW);
    float  a1n = lastc ? a1.w : __ldg(sino + base + PHW + 4);
    float4 c1; float c1n;
    if (!lastv) { c1 = *(const float4*)(sino + base + PHW + DW);
                  c1n = lastc ? c1.w : __ldg(sino + base + PHW + DW + 4); }
    else        { c1 = a1; c1n = a1n; }

    uint4* o = g_q + base;
    o[0] = make_uint4(h2_bits(__floats2half2_rn(a0.x, a0.y)), h2_bits(__floats2half2_rn(c0.x, c0.y)),
                      h2_bits(__floats2half2_rn(a1.x, a1.y)), h2_bits(__floats2half2_rn(c1.x, c1.y)));
    o[1] = make_uint4(h2_bits(__floats2half2_rn(a0.y, a0.z)), h2_bits(__floats2half2_rn(c0.y, c0.z)),
                      h2_bits(__floats2half2_rn(a1.y, a1.z)), h2_bits(__floats2half2_rn(c1.y, c1.z)));
    o[2] = make_uint4(h2_bits(__floats2half2_rn(a0.z, a0.w)), h2_bits(__floats2half2_rn(c0.z, c0.w)),
                      h2_bits(__floats2half2_rn(a1.z, a1.w)), h2_bits(__floats2half2_rn(c1.z, c1.w)));
    o[3] = make_uint4(h2_bits(__floats2half2_rn(a0.w, a0n)),  h2_bits(__floats2half2_rn(c0.w, c0n)),
                      h2_bits(__floats2half2_rn(a1.w, a1n)),  h2_bits(__floats2half2_rn(c1.w, c1n)));
}

__global__ __launch_bounds__(NX, 14)
void cone_bp_kernel(const float* __restrict__ mats,   // [P, 3, 4]
                    float* __restrict__ out)          // [B, Z, Y, X]
{
    // Cone-beam geometry: P[0][2] == P[2][2] == 0 -> u, w independent of z;
    // v affine in z. Both batches share ALL geometry -> fused.
    __shared__ float4 sA[NPROJ];   // (P0, P1*y+P3, P8, P9*y+P11)
    __shared__ float4 sB[NPROJ];   // (P4, P5*y+P7, P6, -)

    const int y  = blockIdx.x;
    const int zc = blockIdx.y;
    const int tx = threadIdx.x;

    const float yw = (float)y - 47.5f;
    for (int p = tx; p < NPROJ; p += NX) {
        const float* P = mats + p * 12;
        sA[p] = make_float4(P[0], fmaf(P[1], yw, P[3]),
                            P[8], fmaf(P[9], yw, P[11]));
        sB[p] = make_float4(P[4], fmaf(P[5], yw, P[7]), P[6], 0.0f);
    }
    __syncthreads();

    const float xw  = (float)tx - 47.5f;
    const float zw0 = (float)(zc * ZPT) - 47.5f;

    float acc0[ZPT], acc1[ZPT];
    #pragma unroll
    for (int j = 0; j < ZPT; ++j) { acc0[j] = 0.0f; acc1[j] = 0.0f; }

    // Two projections per iteration, pipelined:
    //   geom(0) -> loads(0) -> geom(1) -> loads(1) -> math(0) -> math(1)
    // 8 LDG.128s in flight per scoreboard drain. Addresses are kept as
    // 32-bit element offsets (not pointer arrays) to hold register count
    // low enough for 14 resident blocks.
    float   wa[2], wb[2];
    __half2 fv2[2][ZPT];
    uint32_t off[2][ZPT];          // element offset into g_q
    uint4   q[2][ZPT];

    #pragma unroll 1
    for (int p = 0; p < NPROJ; p += 2) {
        #pragma unroll
        for (int s = 0; s < 2; ++s) {
            const float4 A = sA[p + s];
            const float4 B = sB[p + s];

            float uw = fmaf(A.x, xw, A.y);
            float w  = fmaf(A.z, xw, A.w);
            float rw;
            asm("rcp.approx.f32 %0, %1;" : "=f"(rw) : "f"(w));

            float u   = uw * rw;
            float iw2 = rw * rw;

            float uf = floorf(u);
            int   ui = (int)uf;
            float fu = u - uf;
            wb[s] = iw2 * fu;
            wa[s] = iw2 - wb[s];

            float vw0 = fmaf(B.x, xw, B.y);
            float v0  = fmaf(B.z, zw0, vw0) * rw;
            float dv  = B.z * rw;

            uint32_t base = (uint32_t)(p + s) * (DH * DW) + (uint32_t)ui;
            #pragma unroll
            for (int j = 0; j < ZPT; ++j) {
                float v  = fmaf(dv, (float)j, v0);
                float vf = floorf(v);
                fv2[s][j] = __float2half2_rn(v - vf);
                off[s][j] = base + (uint32_t)(int)vf * DW;
            }
            // Issue this projection's loads immediately; s=1 geometry overlaps.
            #pragma unroll
            for (int j = 0; j < ZPT; ++j)
                q[s][j] = __ldg(g_q + off[s][j]);
        }

        #pragma unroll
        for (int s = 0; s < 2; ++s) {
            #pragma unroll
            for (int j = 0; j < ZPT; ++j) {
                __half2 lo0 = bits_h2(q[s][j].x), hi0 = bits_h2(q[s][j].y);
                __half2 c0  = __hfma2(fv2[s][j], __hsub2(hi0, lo0), lo0);
                acc0[j] = fmaf(wa[s], __low2float(c0), fmaf(wb[s], __high2float(c0), acc0[j]));

                __half2 lo1 = bits_h2(q[s][j].z), hi1 = bits_h2(q[s][j].w);
                __half2 c1  = __hfma2(fv2[s][j], __hsub2(hi1, lo1), lo1);
                acc1[j] = fmaf(wa[s], __low2float(c1), fmaf(wb[s], __high2float(c1), acc1[j]));
            }
        }
    }

    const size_t zbase = (size_t)zc * ZPT;
    #pragma unroll
    for (int j = 0; j < ZPT; ++j) {
        out[((zbase + j) * NY + y) * NX + tx]              = acc0[j];
        out[(((size_t)NZ + zbase + j) * NY + y) * NX + tx] = acc1[j];
    }
}

extern "C" void kernel_launch(void* const* d_in, const int* in_sizes, int n_in,
                              void* d_out, int out_size)
{
    const float* sino = (const float*)d_in[0];
    const float* mats = (const float*)d_in[1];
    if (n_in >= 2 && in_sizes[0] == NPROJ * 12) {
        sino = (const float*)d_in[1];
        mats = (const float*)d_in[0];
    }
    float* out = (float*)d_out;

    const size_t groups = PHW / 4;
    prep_quads<<<(unsigned)((groups + 255) / 256), 256>>>(sino);

    dim3 grid(NY, NZ / ZPT, 1);
    cone_bp_kernel<<<grid, NX>>>(mats, out);
}

// round 15
// speedup vs baseline: 1.0019x; 1.0019x over previous
#include <cuda_runtime.h>
#include <cuda_fp16.h>
#include <cstddef>
#include <cstdint>

#define NPROJ 180
#define DH    192
#define DW    384
#define NX    96
#define NY    96
#define NZ    96
#define ZPT   4
#define PHW   ((size_t)NPROJ * DH * DW)

// Scratch: batch-fused bilinear quads at each (p, v, u):
//   .x = (b0: t[v][u], t[v][u+1])   .y = (b0: t[v+1][u], t[v+1][u+1])
//   .z = (b1: t[v][u], t[v][u+1])   .w = (b1: t[v+1][u], t[v+1][u+1])
// One LDG.128 fetches the full 2x2 footprint for BOTH batches. ~212 MB.
__device__ uint4 g_q[PHW];

__device__ __forceinline__ uint32_t h2_bits(__half2 h) {
    union { __half2 h; uint32_t u; } c; c.h = h; return c.u;
}
__device__ __forceinline__ __half2 bits_h2(uint32_t u) {
    union { uint32_t u; __half2 h; } c; c.u = u; return c.h;
}

__global__ void prep_quads(const float* __restrict__ sino) {
    size_t base = ((size_t)blockIdx.x * blockDim.x + threadIdx.x) * 4;
    if (base >= PHW) return;

    int v   = (int)((base / DW) % DH);
    int col = (int)(base % DW);
    bool lastv = (v == DH - 1);
    bool lastc = (col == DW - 4);

    float4 a0 = *(const float4*)(sino + base);
    float  a0n = lastc ? a0.w : __ldg(sino + base + 4);
    float4 c0; float c0n;
    if (!lastv) { c0 = *(const float4*)(sino + base + DW);
                  c0n = lastc ? c0.w : __ldg(sino + base + DW + 4); }
    else        { c0 = a0; c0n = a0n; }

    float4 a1 = *(const float4*)(sino + base + PHW);
    float  a1n = lastc ? a1.w : __ldg(sino + base + PHW + 4);
    float4 c1; float c1n;
    if (!lastv) { c1 = *(const float4*)(sino + base + PHW + DW);
                  c1n = lastc ? c1.w : __ldg(sino + base + PHW + DW + 4); }
    else        { c1 = a1; c1n = a1n; }

    uint4* o = g_q + base;
    o[0] = make_uint4(h2_bits(__floats2half2_rn(a0.x, a0.y)), h2_bits(__floats2half2_rn(c0.x, c0.y)),
                      h2_bits(__floats2half2_rn(a1.x, a1.y)), h2_bits(__floats2half2_rn(c1.x, c1.y)));
    o[1] = make_uint4(h2_bits(__floats2half2_rn(a0.y, a0.z)), h2_bits(__floats2half2_rn(c0.y, c0.z)),
                      h2_bits(__floats2half2_rn(a1.y, a1.z)), h2_bits(__floats2half2_rn(c1.y, c1.z)));
    o[2] = make_uint4(h2_bits(__floats2half2_rn(a0.z, a0.w)), h2_bits(__floats2half2_rn(c0.z, c0.w)),
                      h2_bits(__floats2half2_rn(a1.z, a1.w)), h2_bits(__floats2half2_rn(c1.z, c1.w)));
    o[3] = make_uint4(h2_bits(__floats2half2_rn(a0.w, a0n)),  h2_bits(__floats2half2_rn(c0.w, c0n)),
                      h2_bits(__floats2half2_rn(a1.w, a1n)),  h2_bits(__floats2half2_rn(c1.w, c1n)));
}

__global__ __launch_bounds__(NX, 16)
void cone_bp_kernel(const float* __restrict__ mats,   // [P, 3, 4]
                    float* __restrict__ out)          // [B, Z, Y, X]
{
    // Cone-beam geometry: P[0][2] == P[2][2] == 0 -> u, w independent of z;
    // v affine in z. Both batches share ALL geometry -> fused.
    // Grid = 96*24 = 2304 CTAs; 16 resident blocks/SM * 148 SMs = 2368
    // -> the entire grid runs as ONE wave (no tail wave).
    __shared__ float4 sA[NPROJ];   // (P0, P1*y+P3, P8, P9*y+P11)
    __shared__ float4 sB[NPROJ];   // (P4, P5*y+P7, P6, -)

    const int y  = blockIdx.x;
    const int zc = blockIdx.y;
    const int tx = threadIdx.x;

    const float yw = (float)y - 47.5f;
    for (int p = tx; p < NPROJ; p += NX) {
        const float* P = mats + p * 12;
        sA[p] = make_float4(P[0], fmaf(P[1], yw, P[3]),
                            P[8], fmaf(P[9], yw, P[11]));
        sB[p] = make_float4(P[4], fmaf(P[5], yw, P[7]), P[6], 0.0f);
    }
    __syncthreads();

    const float xw  = (float)tx - 47.5f;
    const float zw0 = (float)(zc * ZPT) - 47.5f;

    float acc0[ZPT], acc1[ZPT];
    #pragma unroll
    for (int j = 0; j < ZPT; ++j) { acc0[j] = 0.0f; acc1[j] = 0.0f; }

    // Two projections per iteration, pipelined:
    //   geom(0) -> loads(0) -> geom(1) -> loads(1) -> math(0) -> math(1)
    // 8 LDG.128s in flight per scoreboard drain. 32-bit element offsets
    // (not pointer arrays) keep register count within the 16-block budget.
    float   wa[2], wb[2];
    __half2 fv2[2][ZPT];
    uint32_t off[2][ZPT];
    uint4   q[2][ZPT];

    #pragma unroll 1
    for (int p = 0; p < NPROJ; p += 2) {
        #pragma unroll
        for (int s = 0; s < 2; ++s) {
            const float4 A = sA[p + s];
            const float4 B = sB[p + s];

            float uw = fmaf(A.x, xw, A.y);
            float w  = fmaf(A.z, xw, A.w);
            float rw;
            asm("rcp.approx.f32 %0, %1;" : "=f"(rw) : "f"(w));

            float u   = uw * rw;
            float iw2 = rw * rw;

            float uf = floorf(u);
            int   ui = (int)uf;
            float fu = u - uf;
            wb[s] = iw2 * fu;
            wa[s] = iw2 - wb[s];

            float vw0 = fmaf(B.x, xw, B.y);
            float v0  = fmaf(B.z, zw0, vw0) * rw;
            float dv  = B.z * rw;

            uint32_t base = (uint32_t)(p + s) * (DH * DW) + (uint32_t)ui;
            #pragma unroll
            for (int j = 0; j < ZPT; ++j) {
                float v  = fmaf(dv, (float)j, v0);
                float vf = floorf(v);
                fv2[s][j] = __float2half2_rn(v - vf);
                off[s][j] = base + (uint32_t)(int)vf * DW;
            }
            // Issue this projection's loads immediately; s=1 geometry overlaps.
            #pragma unroll
            for (int j = 0; j < ZPT; ++j)
                q[s][j] = __ldg(g_q + off[s][j]);
        }

        #pragma unroll
        for (int s = 0; s < 2; ++s) {
            #pragma unroll
            for (int j = 0; j < ZPT; ++j) {
                __half2 lo0 = bits_h2(q[s][j].x), hi0 = bits_h2(q[s][j].y);
                __half2 c0  = __hfma2(fv2[s][j], __hsub2(hi0, lo0), lo0);
                acc0[j] = fmaf(wa[s], __low2float(c0), fmaf(wb[s], __high2float(c0), acc0[j]));

                __half2 lo1 = bits_h2(q[s][j].z), hi1 = bits_h2(q[s][j].w);
                __half2 c1  = __hfma2(fv2[s][j], __hsub2(hi1, lo1), lo1);
                acc1[j] = fmaf(wa[s], __low2float(c1), fmaf(wb[s], __high2float(c1), acc1[j]));
            }
        }
    }

    const size_t zbase = (size_t)zc * ZPT;
    #pragma unroll
    for (int j = 0; j < ZPT; ++j) {
        out[((zbase + j) * NY + y) * NX + tx]              = acc0[j];
        out[(((size_t)NZ + zbase + j) * NY + y) * NX + tx] = acc1[j];
    }
}

extern "C" void kernel_launch(void* const* d_in, const int* in_sizes, int n_in,
                              void* d_out, int out_size)
{
    const float* sino = (const float*)d_in[0];
    const float* mats = (const float*)d_in[1];
    if (n_in >= 2 && in_sizes[0] == NPROJ * 12) {
        sino = (const float*)d_in[1];
        mats = (const float*)d_in[0];
    }
    float* out = (float*)d_out;

    const size_t groups = PHW / 4;
    prep_quads<<<(unsigned)((groups + 255) / 256), 256>>>(sino);

    dim3 grid(NY, NZ / ZPT, 1);
    cone_bp_kernel<<<grid, NX>>>(mats, out);
}

// round 17
// speedup vs baseline: 1.1073x; 1.1052x over previous
#include <cuda_runtime.h>
#include <cuda_fp16.h>
#include <cstddef>
#include <cstdint>

#define NPROJ 180
#define DH    192
#define DW    384
#define NX    96
#define NY    96
#define NZ    96
#define ZPT   4
#define PHW   ((size_t)NPROJ * DH * DW)

// Scratch: batch-fused horizontal pairs at each (p, v, u):
//   .x = (b0: t[v][u], t[v][u+1])  as half2
//   .y = (b1: t[v][u], t[v][u+1])  as half2
// 8 bytes/elem -> 106 MB total: FITS IN L2 (126 MB). Bilinear needs rows v and
// v+1: two LDG.64s, the second at a constant +DW*8 immediate offset.
__device__ uint2 g_p[PHW];

__device__ __forceinline__ uint32_t h2_bits(__half2 h) {
    union { __half2 h; uint32_t u; } c; c.h = h; return c.u;
}
__device__ __forceinline__ __half2 bits_h2(uint32_t u) {
    union { uint32_t u; __half2 h; } c; c.u = u; return c.h;
}

__global__ void prep_pairs(const float* __restrict__ sino) {
    size_t base = ((size_t)blockIdx.x * blockDim.x + threadIdx.x) * 4;
    if (base >= PHW) return;

    int col = (int)(base % DW);
    bool lastc = (col == DW - 4);

    float4 a0 = *(const float4*)(sino + base);
    float  a0n = lastc ? a0.w : __ldg(sino + base + 4);
    float4 a1 = *(const float4*)(sino + base + PHW);
    float  a1n = lastc ? a1.w : __ldg(sino + base + PHW + 4);

    uint2 o[4];
    o[0] = make_uint2(h2_bits(__floats2half2_rn(a0.x, a0.y)), h2_bits(__floats2half2_rn(a1.x, a1.y)));
    o[1] = make_uint2(h2_bits(__floats2half2_rn(a0.y, a0.z)), h2_bits(__floats2half2_rn(a1.y, a1.z)));
    o[2] = make_uint2(h2_bits(__floats2half2_rn(a0.z, a0.w)), h2_bits(__floats2half2_rn(a1.z, a1.w)));
    o[3] = make_uint2(h2_bits(__floats2half2_rn(a0.w, a0n)),  h2_bits(__floats2half2_rn(a1.w, a1n)));

    uint4* dst = (uint4*)(g_p + base);
    dst[0] = *(uint4*)&o[0];
    dst[1] = *(uint4*)&o[2];
}

__global__ __launch_bounds__(NX, 16)
void cone_bp_kernel(const float* __restrict__ mats,   // [P, 3, 4]
                    float* __restrict__ out)          // [B, Z, Y, X]
{
    // Cone-beam geometry: P[0][2] == P[2][2] == 0 -> u, w independent of z;
    // v affine in z. Both batches share ALL geometry -> fused.
    __shared__ float4 sA[NPROJ];   // (P0, P1*y+P3, P8, P9*y+P11)
    __shared__ float4 sB[NPROJ];   // (P4, P5*y+P7, P6, -)

    const int y  = blockIdx.x;
    const int zc = blockIdx.y;
    const int tx = threadIdx.x;

    const float yw = (float)y - 47.5f;
    for (int p = tx; p < NPROJ; p += NX) {
        const float* P = mats + p * 12;
        sA[p] = make_float4(P[0], fmaf(P[1], yw, P[3]),
                            P[8], fmaf(P[9], yw, P[11]));
        sB[p] = make_float4(P[4], fmaf(P[5], yw, P[7]), P[6], 0.0f);
    }
    __syncthreads();

    const float xw  = (float)tx - 47.5f;
    const float zw0 = (float)(zc * ZPT) - 47.5f;

    float acc0[ZPT], acc1[ZPT];
    #pragma unroll
    for (int j = 0; j < ZPT; ++j) { acc0[j] = 0.0f; acc1[j] = 0.0f; }

    // Two projections per iteration, pipelined:
    //   geom(0) -> loads(0) -> geom(1) -> loads(1) -> math(0) -> math(1)
    // 16 LDG.64s in flight per scoreboard drain, mostly L2 hits.
    float   wa[2], wb[2];
    __half2 fv2[2][ZPT];
    uint32_t off[2][ZPT];
    uint2   qlo[2][ZPT], qhi[2][ZPT];

    #pragma unroll 1
    for (int p = 0; p < NPROJ; p += 2) {
        #pragma unroll
        for (int s = 0; s < 2; ++s) {
            const float4 A = sA[p + s];
            const float4 B = sB[p + s];

            float uw = fmaf(A.x, xw, A.y);
            float w  = fmaf(A.z, xw, A.w);
            float rw;
            asm("rcp.approx.f32 %0, %1;" : "=f"(rw) : "f"(w));

            float u   = uw * rw;
            float iw2 = rw * rw;

            float uf = floorf(u);
            int   ui = (int)uf;
            float fu = u - uf;
            wb[s] = iw2 * fu;
            wa[s] = iw2 - wb[s];

            float vw0 = fmaf(B.x, xw, B.y);
            float v0  = fmaf(B.z, zw0, vw0) * rw;
            float dv  = B.z * rw;

            uint32_t base = (uint32_t)(p + s) * (DH * DW) + (uint32_t)ui;
            #pragma unroll
            for (int j = 0; j < ZPT; ++j) {
                float v  = fmaf(dv, (float)j, v0);
                float vf = floorf(v);
                fv2[s][j] = __float2half2_rn(v - vf);
                off[s][j] = base + (uint32_t)(int)vf * DW;
            }
            // Issue this projection's loads immediately; s=1 geometry overlaps.
            // Row v and row v+1 (the +DW is a compile-time immediate offset).
            #pragma unroll
            for (int j = 0; j < ZPT; ++j) {
                qlo[s][j] = __ldg(g_p + off[s][j]);
                qhi[s][j] = __ldg(g_p + off[s][j] + DW);
            }
        }

        #pragma unroll
        for (int s = 0; s < 2; ++s) {
            #pragma unroll
            for (int j = 0; j < ZPT; ++j) {
                __half2 lo0 = bits_h2(qlo[s][j].x), hi0 = bits_h2(qhi[s][j].x);
                __half2 c0  = __hfma2(fv2[s][j], __hsub2(hi0, lo0), lo0);
                acc0[j] = fmaf(wa[s], __low2float(c0), fmaf(wb[s], __high2float(c0), acc0[j]));

                __half2 lo1 = bits_h2(qlo[s][j].y), hi1 = bits_h2(qhi[s][j].y);
                __half2 c1  = __hfma2(fv2[s][j], __hsub2(hi1, lo1), lo1);
                acc1[j] = fmaf(wa[s], __low2float(c1), fmaf(wb[s], __high2float(c1), acc1[j]));
            }
        }
    }

    const size_t zbase = (size_t)zc * ZPT;
    #pragma unroll
    for (int j = 0; j < ZPT; ++j) {
        out[((zbase + j) * NY + y) * NX + tx]              = acc0[j];
        out[(((size_t)NZ + zbase + j) * NY + y) * NX + tx] = acc1[j];
    }
}

extern "C" void kernel_launch(void* const* d_in, const int* in_sizes, int n_in,
                              void* d_out, int out_size)
{
    const float* sino = (const float*)d_in[0];
    const float* mats = (const float*)d_in[1];
    if (n_in >= 2 && in_sizes[0] == NPROJ * 12) {
        sino = (const float*)d_in[1];
        mats = (const float*)d_in[0];
    }
    float* out = (float*)d_out;

    const size_t groups = PHW / 4;
    prep_pairs<<<(unsigned)((groups + 255) / 256), 256>>>(sino);

    dim3 grid(NY, NZ / ZPT, 1);
    cone_bp_kernel<<<grid, NX>>>(mats, out);
}